// round 11
// baseline (speedup 1.0000x reference)
#include <cuda_runtime.h>

// FocalBCELoss: mean over [N,C] of -( t*log(p)*(1-p)^2*alpha[c] + (1-t)*log(1-p)*p^2 )
// N=262144, C=64, gamma=2.0.
// Identity used: with q = (t ? p : 1-p) and s = (t ? alpha : 1),
//   elem = log(q) * (1-q)^2 * s   for both t=0 and t=1.
// Single streaming kernel, fixed 8-iteration fully-unrolled loop (front-batched
// LDG.128 for MLP), last-block final reduction.

#define FB_N       262144
#define FB_C       64
#define FB_TOTAL   (FB_N * FB_C)          // 16,777,216 floats
#define FB_N4      (FB_TOTAL / 4)         // 4,194,304 float4s

#define NBLOCKS    2048
#define NTHREADS   256
#define NTHR_TOT   (NBLOCKS * NTHREADS)   // 524,288 threads
#define ITERS      (FB_N4 / NTHR_TOT)     // exactly 8

__device__ float        g_partials[NBLOCKS];
__device__ unsigned int g_done_count = 0;

// elem = log(q)*(1-q)^2*scale ; am1 = alpha-1 so scale = fmaf(t, am1, 1)
__device__ __forceinline__ float felem(float p, float t, float am1) {
    float u   = 1.0f - p;
    float q   = fmaf(t, p - u, u);        // t? p : 1-p
    float omq = 1.0f - q;
    float s   = fmaf(t, am1, 1.0f);       // t? alpha : 1
    float lg  = __logf(q);                // single MUFU.LG2 path
    return lg * omq * omq * s;
}

__device__ __forceinline__ float block_reduce(float acc, float* smem) {
    const int lane = threadIdx.x & 31;
    const int wid  = threadIdx.x >> 5;
    #pragma unroll
    for (int off = 16; off > 0; off >>= 1)
        acc += __shfl_down_sync(0xFFFFFFFFu, acc, off);
    if (lane == 0) smem[wid] = acc;
    __syncthreads();
    float v = 0.0f;
    if (wid == 0) {
        v = (lane < NTHREADS / 32) ? smem[lane] : 0.0f;
        #pragma unroll
        for (int off = 4; off > 0; off >>= 1)
            v += __shfl_down_sync(0xFFFFFFFFu, v, off);
    }
    return v;   // valid on thread 0
}

__global__ __launch_bounds__(NTHREADS)
void focal_fused_kernel(const float4* __restrict__ in4,
                        const float4* __restrict__ tg4,
                        const float*  __restrict__ alpha,
                        float* __restrict__ out) {
    const int tid = blockIdx.x * NTHREADS + threadIdx.x;

    // Column base is constant per thread: stride*4 = 2,097,152 floats, %64 == 0.
    const int cb = (tid * 4) & (FB_C - 1);
    const float a0 = __ldg(alpha + cb + 0) - 1.0f;
    const float a1 = __ldg(alpha + cb + 1) - 1.0f;
    const float a2 = __ldg(alpha + cb + 2) - 1.0f;
    const float a3 = __ldg(alpha + cb + 3) - 1.0f;

    float accx = 0.0f, accy = 0.0f, accz = 0.0f, accw = 0.0f;

    #pragma unroll
    for (int k = 0; k < ITERS; k++) {
        const int idx = tid + k * NTHR_TOT;      // compile-time offsets
        float4 p = __ldcs(in4 + idx);            // streaming: read-once data
        float4 t = __ldcs(tg4 + idx);
        accx += felem(p.x, t.x, a0);
        accy += felem(p.y, t.y, a1);
        accz += felem(p.z, t.z, a2);
        accw += felem(p.w, t.w, a3);
    }
    float acc = (accx + accy) + (accz + accw);

    __shared__ float smem[NTHREADS / 32];
    float bsum = block_reduce(acc, smem);

    __shared__ bool is_last;
    if (threadIdx.x == 0) {
        g_partials[blockIdx.x] = bsum;
        __threadfence();                         // partial visible before count bump
        unsigned int old = atomicAdd(&g_done_count, 1u);
        is_last = (old == NBLOCKS - 1);
    }
    __syncthreads();

    if (is_last) {
        float facc = 0.0f;
        for (int i = threadIdx.x; i < NBLOCKS; i += NTHREADS)  // fixed order: deterministic
            facc += g_partials[i];
        __syncthreads();                         // smem reuse safe
        float fsum = block_reduce(facc, smem);
        if (threadIdx.x == 0) {
            out[0] = -fsum * (1.0f / (float)FB_TOTAL);
            g_done_count = 0;                    // reset for next graph replay
        }
    }
}

extern "C" void kernel_launch(void* const* d_in, const int* in_sizes, int n_in,
                              void* d_out, int out_size) {
    const float4* in4   = (const float4*)d_in[0];   // inputs  [N,C] f32
    const float4* tg4   = (const float4*)d_in[1];   // targets [N,C] f32
    const float*  alpha = (const float*)d_in[2];    // alpha   [C]   f32
    float* out = (float*)d_out;

    focal_fused_kernel<<<NBLOCKS, NTHREADS>>>(in4, tg4, alpha, out);
}

// round 13
// speedup vs baseline: 1.0468x; 1.0468x over previous
#include <cuda_runtime.h>

// FocalBCELoss: mean over [N,C] of -( t*log(p)*(1-p)^2*alpha[c] + (1-t)*log(1-p)*p^2 )
// N=262144, C=64, gamma=2.0.
// Identity: with q = (t ? p : 1-p) and s = (t ? alpha : 1),
//   elem = log(q) * (1-q)^2 * s   for both t=0 and t=1   (one log instead of two).
// R6-proven launch shape: grid-stride, 1184 blocks x 256, __ldg, low regs / high occ.

#define FB_N       262144
#define FB_C       64
#define FB_TOTAL   (FB_N * FB_C)          // 16,777,216 floats
#define FB_N4      (FB_TOTAL / 4)         // 4,194,304 float4s (exact)

#define NBLOCKS    1184                   // 148 SMs * 8
#define NTHREADS   256

__device__ float        g_partials[NBLOCKS];
__device__ unsigned int g_done_count = 0;

// elem = log(q)*(1-q)^2*s ; am1 = alpha-1 so s = fmaf(t, am1, 1)
__device__ __forceinline__ float felem(float p, float t, float am1) {
    float u   = 1.0f - p;
    float q   = fmaf(t, p - u, u);        // t? p : 1-p   (t is exactly 0 or 1)
    float omq = 1.0f - q;
    float s   = fmaf(t, am1, 1.0f);       // t? alpha : 1
    float lg  = __logf(q);                // single MUFU.LG2 path
    return lg * omq * omq * s;
}

__device__ __forceinline__ float block_reduce(float acc, float* smem) {
    const int lane = threadIdx.x & 31;
    const int wid  = threadIdx.x >> 5;
    #pragma unroll
    for (int off = 16; off > 0; off >>= 1)
        acc += __shfl_down_sync(0xFFFFFFFFu, acc, off);
    if (lane == 0) smem[wid] = acc;
    __syncthreads();
    float v = 0.0f;
    if (wid == 0) {
        v = (lane < NTHREADS / 32) ? smem[lane] : 0.0f;
        #pragma unroll
        for (int off = 4; off > 0; off >>= 1)
            v += __shfl_down_sync(0xFFFFFFFFu, v, off);
    }
    return v;   // valid on thread 0
}

__global__ __launch_bounds__(NTHREADS)
void focal_fused_kernel(const float4* __restrict__ in4,
                        const float4* __restrict__ tg4,
                        const float*  __restrict__ alpha,
                        float* __restrict__ out) {
    const int tid    = blockIdx.x * NTHREADS + threadIdx.x;
    const int stride = NBLOCKS * NTHREADS;          // float4 stride; *4 % 64 == 0

    // Column base constant per thread (row = 16 float4s; stride multiple of 16)
    const int cb = (tid * 4) & (FB_C - 1);
    const float a0 = __ldg(alpha + cb + 0) - 1.0f;
    const float a1 = __ldg(alpha + cb + 1) - 1.0f;
    const float a2 = __ldg(alpha + cb + 2) - 1.0f;
    const float a3 = __ldg(alpha + cb + 3) - 1.0f;

    float accx = 0.0f, accy = 0.0f, accz = 0.0f, accw = 0.0f;
    for (int i = tid; i < FB_N4; i += stride) {
        float4 p = __ldg(in4 + i);
        float4 t = __ldg(tg4 + i);
        accx += felem(p.x, t.x, a0);
        accy += felem(p.y, t.y, a1);
        accz += felem(p.z, t.z, a2);
        accw += felem(p.w, t.w, a3);
    }
    float acc = (accx + accy) + (accz + accw);

    __shared__ float smem[NTHREADS / 32];
    float bsum = block_reduce(acc, smem);

    __shared__ bool is_last;
    if (threadIdx.x == 0) {
        g_partials[blockIdx.x] = bsum;
        __threadfence();                             // partial visible before count bump
        unsigned int old = atomicAdd(&g_done_count, 1u);
        is_last = (old == NBLOCKS - 1);
    }
    __syncthreads();

    if (is_last) {
        float facc = 0.0f;
        for (int i = threadIdx.x; i < NBLOCKS; i += NTHREADS)   // fixed order: deterministic
            facc += g_partials[i];
        __syncthreads();                             // smem reuse safe
        float fsum = block_reduce(facc, smem);
        if (threadIdx.x == 0) {
            out[0] = -fsum * (1.0f / (float)FB_TOTAL);
            g_done_count = 0;                        // reset for next graph replay
        }
    }
}

extern "C" void kernel_launch(void* const* d_in, const int* in_sizes, int n_in,
                              void* d_out, int out_size) {
    const float4* in4   = (const float4*)d_in[0];   // inputs  [N,C] f32
    const float4* tg4   = (const float4*)d_in[1];   // targets [N,C] f32
    const float*  alpha = (const float*)d_in[2];    // alpha   [C]   f32
    float* out = (float*)d_out;

    focal_fused_kernel<<<NBLOCKS, NTHREADS>>>(in4, tg4, alpha, out);
}

// round 14
// speedup vs baseline: 1.0696x; 1.0217x over previous
#include <cuda_runtime.h>

// FocalBCELoss: mean over [N,C] of -( t*log(p)*(1-p)^2*alpha[c] + (1-t)*log(1-p)*p^2 )
// N=262144, C=64, gamma=2.0.
// Identity: q = (t ? p : 1-p), s = (t ? alpha : 1)  ->  elem = log(q)*(1-q)^2*s.
// This round: MLP_p1=4 (front-batched 4x LDG.128 per iteration), clean bounds
// (FB_N4 % (2*stride) == 0), reg budget 42 via __launch_bounds__, occ ~75%.

#define FB_N       262144
#define FB_C       64
#define FB_TOTAL   (FB_N * FB_C)          // 16,777,216 floats
#define FB_N4      (FB_TOTAL / 4)         // 4,194,304 float4s (2^22)

#define NBLOCKS    1024
#define NTHREADS   256
#define STRIDE4    (NBLOCKS * NTHREADS)   // 262,144 float4s
#define DITERS     (FB_N4 / (2 * STRIDE4))// exactly 8 double-iterations

__device__ float        g_partials[NBLOCKS];
__device__ unsigned int g_done_count = 0;

// elem = log(q)*(1-q)^2*s ; am1 = alpha-1 so s = fmaf(t, am1, 1)
__device__ __forceinline__ float felem(float p, float t, float am1) {
    float u   = 1.0f - p;
    float q   = fmaf(t, p - u, u);        // t? p : 1-p   (t is exactly 0 or 1)
    float omq = 1.0f - q;
    float s   = fmaf(t, am1, 1.0f);       // t? alpha : 1
    float lg  = __logf(q);                // single MUFU.LG2 path
    return lg * omq * omq * s;
}

__device__ __forceinline__ float block_reduce(float acc, float* smem) {
    const int lane = threadIdx.x & 31;
    const int wid  = threadIdx.x >> 5;
    #pragma unroll
    for (int off = 16; off > 0; off >>= 1)
        acc += __shfl_down_sync(0xFFFFFFFFu, acc, off);
    if (lane == 0) smem[wid] = acc;
    __syncthreads();
    float v = 0.0f;
    if (wid == 0) {
        v = (lane < NTHREADS / 32) ? smem[lane] : 0.0f;
        #pragma unroll
        for (int off = 4; off > 0; off >>= 1)
            v += __shfl_down_sync(0xFFFFFFFFu, v, off);
    }
    return v;   // valid on thread 0
}

__global__ __launch_bounds__(NTHREADS, 6)   // 42-reg budget -> 6 blocks/SM
void focal_fused_kernel(const float4* __restrict__ in4,
                        const float4* __restrict__ tg4,
                        const float*  __restrict__ alpha,
                        float* __restrict__ out) {
    const int tid = blockIdx.x * NTHREADS + threadIdx.x;

    // Column base constant per thread: STRIDE4*4 = 1,048,576 floats, % 64 == 0,
    // and both offsets (i, i+STRIDE4) share the same column base.
    const int cb = (tid * 4) & (FB_C - 1);
    const float a0 = __ldg(alpha + cb + 0) - 1.0f;
    const float a1 = __ldg(alpha + cb + 1) - 1.0f;
    const float a2 = __ldg(alpha + cb + 2) - 1.0f;
    const float a3 = __ldg(alpha + cb + 3) - 1.0f;

    float accx = 0.0f, accy = 0.0f, accz = 0.0f, accw = 0.0f;

    #pragma unroll 1                        // keep live ranges bounded (regs ~40)
    for (int k = 0; k < DITERS; k++) {
        const int i = tid + k * (2 * STRIDE4);
        // Front-batch 4 independent LDG.128s (MLP_p1 = 4)
        float4 p0 = __ldg(in4 + i);
        float4 p1 = __ldg(in4 + i + STRIDE4);
        float4 t0 = __ldg(tg4 + i);
        float4 t1 = __ldg(tg4 + i + STRIDE4);

        accx += felem(p0.x, t0.x, a0);
        accy += felem(p0.y, t0.y, a1);
        accz += felem(p0.z, t0.z, a2);
        accw += felem(p0.w, t0.w, a3);
        accx += felem(p1.x, t1.x, a0);
        accy += felem(p1.y, t1.y, a1);
        accz += felem(p1.z, t1.z, a2);
        accw += felem(p1.w, t1.w, a3);
    }
    float acc = (accx + accy) + (accz + accw);

    __shared__ float smem[NTHREADS / 32];
    float bsum = block_reduce(acc, smem);

    __shared__ bool is_last;
    if (threadIdx.x == 0) {
        g_partials[blockIdx.x] = bsum;
        __threadfence();                     // partial visible before count bump
        unsigned int old = atomicAdd(&g_done_count, 1u);
        is_last = (old == NBLOCKS - 1);
    }
    __syncthreads();

    if (is_last) {
        float facc = 0.0f;
        for (int i = threadIdx.x; i < NBLOCKS; i += NTHREADS)  // fixed order: deterministic
            facc += g_partials[i];
        __syncthreads();                     // smem reuse safe
        float fsum = block_reduce(facc, smem);
        if (threadIdx.x == 0) {
            out[0] = -fsum * (1.0f / (float)FB_TOTAL);
            g_done_count = 0;                // reset for next graph replay
        }
    }
}

extern "C" void kernel_launch(void* const* d_in, const int* in_sizes, int n_in,
                              void* d_out, int out_size) {
    const float4* in4   = (const float4*)d_in[0];   // inputs  [N,C] f32
    const float4* tg4   = (const float4*)d_in[1];   // targets [N,C] f32
    const float*  alpha = (const float*)d_in[2];    // alpha   [C]   f32
    float* out = (float*)d_out;

    focal_fused_kernel<<<NBLOCKS, NTHREADS>>>(in4, tg4, alpha, out);
}

// round 15
// speedup vs baseline: 1.0789x; 1.0088x over previous
#include <cuda_runtime.h>

// FocalBCELoss: mean over [N,C] of -( t*log(p)*(1-p)^2*alpha[c] + (1-t)*log(1-p)*p^2 )
// N=262144, C=64, gamma=2.0.
// Identity: q = (t ? p : 1-p), s = (t ? alpha : 1)  ->  elem = log(q)*(1-q)^2*s.
// This round:
//  - block-CONTIGUOUS chunking (sequential 4KB steps per block) for DRAM row locality
//  - deterministic fixed-point RED.ADD.64 tail + tiny finisher kernel (no serial
//    float reduction, no atomic return round-trips, bitwise deterministic)

#define FB_N       262144
#define FB_C       64
#define FB_TOTAL   (FB_N * FB_C)            // 16,777,216 floats
#define FB_N4      (FB_TOTAL / 4)           // 4,194,304 float4s (2^22)

#define NBLOCKS    1024
#define NTHREADS   256
#define CHUNK4     (FB_N4 / NBLOCKS)        // 4096 float4s per block (contiguous)
#define ITERS      (CHUNK4 / NTHREADS)      // exactly 16

#define FPSCALE    1073741824.0             // 2^30 fixed-point scale

__device__ long long g_isum = 0;            // exact integer accumulator

// elem = log(q)*(1-q)^2*s ; am1 = alpha-1 so s = fmaf(t, am1, 1)
__device__ __forceinline__ float felem(float p, float t, float am1) {
    float u   = 1.0f - p;
    float q   = fmaf(t, p - u, u);          // t? p : 1-p   (t is exactly 0 or 1)
    float omq = 1.0f - q;
    float s   = fmaf(t, am1, 1.0f);         // t? alpha : 1
    float lg  = __logf(q);                  // single MUFU.LG2 path
    return lg * omq * omq * s;
}

__device__ __forceinline__ float block_reduce(float acc, float* smem) {
    const int lane = threadIdx.x & 31;
    const int wid  = threadIdx.x >> 5;
    #pragma unroll
    for (int off = 16; off > 0; off >>= 1)
        acc += __shfl_down_sync(0xFFFFFFFFu, acc, off);
    if (lane == 0) smem[wid] = acc;
    __syncthreads();
    float v = 0.0f;
    if (wid == 0) {
        v = (lane < NTHREADS / 32) ? smem[lane] : 0.0f;
        #pragma unroll
        for (int off = 4; off > 0; off >>= 1)
            v += __shfl_down_sync(0xFFFFFFFFu, v, off);
    }
    return v;   // valid on thread 0
}

__global__ __launch_bounds__(NTHREADS)
void focal_main_kernel(const float4* __restrict__ in4,
                       const float4* __restrict__ tg4,
                       const float*  __restrict__ alpha) {
    // Block-contiguous region: block b owns float4s [b*CHUNK4, (b+1)*CHUNK4).
    // Each iteration the block reads one contiguous 4KB slab per array, and
    // consecutive iterations are address-sequential (DRAM row friendly).
    const int base = blockIdx.x * CHUNK4 + threadIdx.x;

    // Column base constant per thread: NTHREADS*4 = 1024 floats == 0 mod 64,
    // and block base CHUNK4*4 = 16384 floats == 0 mod 64.
    const int cb = (threadIdx.x * 4) & (FB_C - 1);
    const float a0 = __ldg(alpha + cb + 0) - 1.0f;
    const float a1 = __ldg(alpha + cb + 1) - 1.0f;
    const float a2 = __ldg(alpha + cb + 2) - 1.0f;
    const float a3 = __ldg(alpha + cb + 3) - 1.0f;

    float accx = 0.0f, accy = 0.0f, accz = 0.0f, accw = 0.0f;

    #pragma unroll 1                         // keep regs ~32, occupancy high
    for (int k = 0; k < ITERS; k++) {
        const int i = base + k * NTHREADS;
        float4 p = __ldg(in4 + i);
        float4 t = __ldg(tg4 + i);
        accx += felem(p.x, t.x, a0);
        accy += felem(p.y, t.y, a1);
        accz += felem(p.z, t.z, a2);
        accw += felem(p.w, t.w, a3);
    }
    float acc = (accx + accy) + (accz + accw);

    __shared__ float smem[NTHREADS / 32];
    float bsum = block_reduce(acc, smem);

    if (threadIdx.x == 0) {
        // Fixed-point contribution: integer adds are associative -> bitwise
        // deterministic regardless of arrival order. Fire-and-forget RED.
        long long q = __double2ll_rn((double)bsum * FPSCALE);
        atomicAdd((unsigned long long*)&g_isum, (unsigned long long)q);
    }
}

__global__ void focal_finish_kernel(float* __restrict__ out) {
    if (threadIdx.x == 0) {
        double s = (double)g_isum * (1.0 / FPSCALE);
        out[0] = (float)(-s / (double)FB_TOTAL);
        g_isum = 0;                          // reset for next graph replay
    }
}

extern "C" void kernel_launch(void* const* d_in, const int* in_sizes, int n_in,
                              void* d_out, int out_size) {
    const float4* in4   = (const float4*)d_in[0];   // inputs  [N,C] f32
    const float4* tg4   = (const float4*)d_in[1];   // targets [N,C] f32
    const float*  alpha = (const float*)d_in[2];    // alpha   [C]   f32
    float* out = (float*)d_out;

    focal_main_kernel<<<NBLOCKS, NTHREADS>>>(in4, tg4, alpha);
    focal_finish_kernel<<<1, 32>>>(out);
}

// round 16
// speedup vs baseline: 1.0958x; 1.0156x over previous
#include <cuda_runtime.h>

// FocalBCELoss: mean over [N,C] of -( t*log(p)*(1-p)^2*alpha[c] + (1-t)*log(1-p)*p^2 )
// N=262144, C=64, gamma=2.0.
// Identity: q = (t ? p : 1-p), s = (t ? alpha : 1)  ->  elem = log(q)*(1-q)^2*s.
// This round: SINGLE kernel (second launch measured 3.6-5.6us of pure overhead).
//  - block-contiguous chunks (best-measured loop, R15)
//  - fixed-point RED.ADD.64 partial per block (associative -> bitwise deterministic)
//  - last block converts/scales/writes out[0] and resets state (no finisher kernel)

#define FB_N       262144
#define FB_C       64
#define FB_TOTAL   (FB_N * FB_C)            // 16,777,216 floats
#define FB_N4      (FB_TOTAL / 4)           // 4,194,304 float4s (2^22)

#define NBLOCKS    1024
#define NTHREADS   256
#define CHUNK4     (FB_N4 / NBLOCKS)        // 4096 float4s per block (contiguous)
#define ITERS      (CHUNK4 / NTHREADS)      // exactly 16

#define FPSCALE    1073741824.0             // 2^30 fixed-point scale

__device__ long long    g_isum = 0;         // exact integer accumulator
__device__ unsigned int g_done_count = 0;

// elem = log(q)*(1-q)^2*s ; am1 = alpha-1 so s = fmaf(t, am1, 1)
__device__ __forceinline__ float felem(float p, float t, float am1) {
    float u   = 1.0f - p;
    float q   = fmaf(t, p - u, u);          // t? p : 1-p   (t is exactly 0 or 1)
    float omq = 1.0f - q;
    float s   = fmaf(t, am1, 1.0f);         // t? alpha : 1
    float lg  = __logf(q);                  // single MUFU.LG2 path
    return lg * omq * omq * s;
}

__device__ __forceinline__ float block_reduce(float acc, float* smem) {
    const int lane = threadIdx.x & 31;
    const int wid  = threadIdx.x >> 5;
    #pragma unroll
    for (int off = 16; off > 0; off >>= 1)
        acc += __shfl_down_sync(0xFFFFFFFFu, acc, off);
    if (lane == 0) smem[wid] = acc;
    __syncthreads();
    float v = 0.0f;
    if (wid == 0) {
        v = (lane < NTHREADS / 32) ? smem[lane] : 0.0f;
        #pragma unroll
        for (int off = 4; off > 0; off >>= 1)
            v += __shfl_down_sync(0xFFFFFFFFu, v, off);
    }
    return v;   // valid on thread 0
}

__global__ __launch_bounds__(NTHREADS)
void focal_fused_kernel(const float4* __restrict__ in4,
                        const float4* __restrict__ tg4,
                        const float*  __restrict__ alpha,
                        float* __restrict__ out) {
    // Block-contiguous region: block b owns float4s [b*CHUNK4, (b+1)*CHUNK4).
    // Consecutive iterations are address-sequential (DRAM row friendly).
    const int base = blockIdx.x * CHUNK4 + threadIdx.x;

    // Column base constant per thread: NTHREADS*4 = 1024 == 0 mod 64,
    // block base CHUNK4*4 = 16384 == 0 mod 64.
    const int cb = (threadIdx.x * 4) & (FB_C - 1);
    const float a0 = __ldg(alpha + cb + 0) - 1.0f;
    const float a1 = __ldg(alpha + cb + 1) - 1.0f;
    const float a2 = __ldg(alpha + cb + 2) - 1.0f;
    const float a3 = __ldg(alpha + cb + 3) - 1.0f;

    float accx = 0.0f, accy = 0.0f, accz = 0.0f, accw = 0.0f;

    #pragma unroll 1                         // keep regs ~32, occupancy high
    for (int k = 0; k < ITERS; k++) {
        const int i = base + k * NTHREADS;
        float4 p = __ldg(in4 + i);
        float4 t = __ldg(tg4 + i);
        accx += felem(p.x, t.x, a0);
        accy += felem(p.y, t.y, a1);
        accz += felem(p.z, t.z, a2);
        accw += felem(p.w, t.w, a3);
    }
    float acc = (accx + accy) + (accz + accw);

    __shared__ float smem[NTHREADS / 32];
    float bsum = block_reduce(acc, smem);

    __shared__ bool is_last;
    if (threadIdx.x == 0) {
        // Fixed-point partial: integer adds are associative -> bitwise
        // deterministic regardless of arrival order.
        long long q = __double2ll_rn((double)bsum * FPSCALE);
        atomicAdd((unsigned long long*)&g_isum, (unsigned long long)q);
        __threadfence();                     // RED visible before count bump
        unsigned int old = atomicAdd(&g_done_count, 1u);
        is_last = (old == NBLOCKS - 1);
    }
    __syncthreads();

    if (is_last && threadIdx.x == 0) {
        __threadfence();                     // order: counter observed -> isum read
        // Read-and-reset atomically; all 1023 other partials are in (their fence
        // precedes the counter bump we observed).
        long long v = (long long)atomicExch((unsigned long long*)&g_isum, 0ull);
        double s = (double)v * (1.0 / FPSCALE);
        out[0] = (float)(-s / (double)FB_TOTAL);
        g_done_count = 0;                    // reset for next graph replay
    }
}

extern "C" void kernel_launch(void* const* d_in, const int* in_sizes, int n_in,
                              void* d_out, int out_size) {
    const float4* in4   = (const float4*)d_in[0];   // inputs  [N,C] f32
    const float4* tg4   = (const float4*)d_in[1];   // targets [N,C] f32
    const float*  alpha = (const float*)d_in[2];    // alpha   [C]   f32
    float* out = (float*)d_out;

    focal_fused_kernel<<<NBLOCKS, NTHREADS>>>(in4, tg4, alpha, out);
}